// round 1
// baseline (speedup 1.0000x reference)
#include <cuda_runtime.h>
#include <math.h>

// Problem constants
#define NPIX   131072      // B*H*W = 8*128*128
#define BATCH  8
#define HH     128
#define WW     128
#define CDIM   192
#define C3     576         // 3*CDIM
#define HEADS  6
#define HD     32          // head dim
#define HID    510
#define HID2   1020        // 2*HID
#define UGLD   512         // padded lda for gated ffn activation
#define NPB    16384       // pixels per batch

// ---------------- scratch (device globals; allocation-free rule) ----------------
__device__ float g_y[(size_t)NPIX * CDIM];
__device__ float g_qkv_pre[(size_t)NPIX * C3];
__device__ float g_qkv[(size_t)NPIX * C3];
__device__ float g_part[48 * 16 * 1024];     // partial K^T Q sums, 16 chunks
__device__ float g_attn[48 * 1024];
__device__ float g_W2[BATCH * CDIM * CDIM];  // attn folded into w_proj, per batch
__device__ float g_x1[(size_t)NPIX * CDIM];
__device__ float g_upre[(size_t)NPIX * HID2];
__device__ float g_ug[(size_t)NPIX * UGLD];

// ---------------- LayerNorm (one warp per pixel, C=192 = 6 per lane) ----------------
__global__ void ln_kernel(const float* __restrict__ x, const float* __restrict__ g,
                          const float* __restrict__ b, float* __restrict__ y) {
    size_t warp = ((size_t)blockIdx.x * blockDim.x + threadIdx.x) >> 5;
    int lane = threadIdx.x & 31;
    const float* xr = x + warp * CDIM;
    float v[6]; float s = 0.f, s2 = 0.f;
#pragma unroll
    for (int i = 0; i < 6; i++) { v[i] = xr[lane + 32 * i]; s += v[i]; s2 += v[i] * v[i]; }
#pragma unroll
    for (int o = 16; o; o >>= 1) {
        s  += __shfl_xor_sync(0xffffffffu, s, o);
        s2 += __shfl_xor_sync(0xffffffffu, s2, o);
    }
    float mu  = s * (1.f / CDIM);
    float var = s2 * (1.f / CDIM) - mu * mu;
    float rs = rsqrtf(var + 1e-3f);
    float* yr = y + warp * CDIM;
#pragma unroll
    for (int i = 0; i < 6; i++) {
        int c = lane + 32 * i;
        yr[c] = (v[i] - mu) * rs * g[c] + b[c];
    }
}

// ---------------- generic tiled GEMM: C = A(:,aoff:aoff+K) * B (+R), batched over z ----
__global__ void __launch_bounds__(256) gemm_kernel(
    const float* __restrict__ A, int lda, int aoff,
    const float* __restrict__ B, int bstride,
    const float* __restrict__ R,
    float* __restrict__ C,
    int Nper, int K, int M)
{
    int bz = blockIdx.z;
    A += (size_t)bz * Nper * lda;
    B += (size_t)bz * bstride;
    if (R) R += (size_t)bz * Nper * M;
    C += (size_t)bz * (size_t)Nper * M;

    __shared__ __align__(16) float As[16][65];
    __shared__ __align__(16) float Bs[16][64];

    int tid = threadIdx.x;
    int row0 = blockIdx.y * 64;
    int col0 = blockIdx.x * 64;
    int tx = tid & 15, ty = tid >> 4;

    int arow = tid >> 2, ak4 = (tid & 3) << 2;
    int bk = tid >> 4, bm4 = (tid & 15) << 2;
    bool mfull = (col0 + 64 <= M);

    float acc[4][4] = {};

    for (int k0 = 0; k0 < K; k0 += 16) {
        const float* Ap = A + (size_t)(row0 + arow) * lda + aoff + k0 + ak4;
        if (k0 + 16 <= K) {
            float4 v = *reinterpret_cast<const float4*>(Ap);
            As[ak4 + 0][arow] = v.x; As[ak4 + 1][arow] = v.y;
            As[ak4 + 2][arow] = v.z; As[ak4 + 3][arow] = v.w;
        } else {
#pragma unroll
            for (int j = 0; j < 4; j++)
                As[ak4 + j][arow] = (k0 + ak4 + j < K) ? Ap[j] : 0.f;
        }
        bool kok = (k0 + bk < K);
        const float* Bp = B + (size_t)(k0 + bk) * M + col0 + bm4;
        if (kok && mfull) {
            *reinterpret_cast<float4*>(&Bs[bk][bm4]) = *reinterpret_cast<const float4*>(Bp);
        } else {
#pragma unroll
            for (int j = 0; j < 4; j++)
                Bs[bk][bm4 + j] = (kok && (col0 + bm4 + j < M)) ? Bp[j] : 0.f;
        }
        __syncthreads();
#pragma unroll
        for (int kk = 0; kk < 16; kk++) {
            float a0 = As[kk][ty * 4 + 0];
            float a1 = As[kk][ty * 4 + 1];
            float a2 = As[kk][ty * 4 + 2];
            float a3 = As[kk][ty * 4 + 3];
            float4 bv = *reinterpret_cast<const float4*>(&Bs[kk][tx * 4]);
            acc[0][0] += a0 * bv.x; acc[0][1] += a0 * bv.y; acc[0][2] += a0 * bv.z; acc[0][3] += a0 * bv.w;
            acc[1][0] += a1 * bv.x; acc[1][1] += a1 * bv.y; acc[1][2] += a1 * bv.z; acc[1][3] += a1 * bv.w;
            acc[2][0] += a2 * bv.x; acc[2][1] += a2 * bv.y; acc[2][2] += a2 * bv.z; acc[2][3] += a2 * bv.w;
            acc[3][0] += a3 * bv.x; acc[3][1] += a3 * bv.y; acc[3][2] += a3 * bv.z; acc[3][3] += a3 * bv.w;
        }
        __syncthreads();
    }
#pragma unroll
    for (int i = 0; i < 4; i++) {
        size_t row = (size_t)row0 + ty * 4 + i;
        float* Cp = C + row * M + col0 + tx * 4;
        if (mfull) {
            float4 o = make_float4(acc[i][0], acc[i][1], acc[i][2], acc[i][3]);
            if (R) {
                float4 r = *reinterpret_cast<const float4*>(R + row * M + col0 + tx * 4);
                o.x += r.x; o.y += r.y; o.z += r.z; o.w += r.w;
            }
            *reinterpret_cast<float4*>(Cp) = o;
        } else {
#pragma unroll
            for (int j = 0; j < 4; j++) {
                int col = col0 + tx * 4 + j;
                if (col < M) {
                    float o = acc[i][j];
                    if (R) o += R[row * M + col];
                    Cp[j] = o;
                }
            }
        }
    }
}

// ---------------- depthwise 3x3 SAME conv, NHWC, one block per pixel ----------------
__global__ void dwconv_kernel(const float* __restrict__ in, const float* __restrict__ w,
                              float* __restrict__ out, int C) {
    int p = blockIdx.x;
    int c = threadIdx.x;
    int b = p >> 14, hw = p & 16383, yy = hw >> 7, xx = hw & 127;
    float acc = 0.f;
#pragma unroll
    for (int ky = -1; ky <= 1; ky++) {
        int yn = yy + ky;
        if ((unsigned)yn >= HH) continue;
#pragma unroll
        for (int kx = -1; kx <= 1; kx++) {
            int xn = xx + kx;
            if ((unsigned)xn >= WW) continue;
            size_t idx = ((size_t)(b << 14) + (yn << 7) + xn) * C + c;
            acc += in[idx] * w[((ky + 1) * 3 + (kx + 1)) * C + c];
        }
    }
    out[(size_t)p * C + c] = acc;
}

// ---------------- FFN depthwise 3x3 + exact-GELU gating fused ----------------
__global__ void dwconv_ffn_gate(const float* __restrict__ in, const float* __restrict__ w,
                                float* __restrict__ out) {
    int p = blockIdx.x;
    int c = threadIdx.x;          // blockDim = 512
    if (c >= HID) return;
    int b = p >> 14, hw = p & 16383, yy = hw >> 7, xx = hw & 127;
    float a1 = 0.f, a2 = 0.f;
#pragma unroll
    for (int ky = -1; ky <= 1; ky++) {
        int yn = yy + ky;
        if ((unsigned)yn >= HH) continue;
#pragma unroll
        for (int kx = -1; kx <= 1; kx++) {
            int xn = xx + kx;
            if ((unsigned)xn >= WW) continue;
            size_t idx = ((size_t)(b << 14) + (yn << 7) + xn) * HID2;
            int wi = ((ky + 1) * 3 + (kx + 1)) * HID2;
            a1 += in[idx + c]        * w[wi + c];
            a2 += in[idx + HID + c]  * w[wi + HID + c];
        }
    }
    float gl = 0.5f * a1 * (1.f + erff(a1 * 0.70710678118654752f));
    out[(size_t)p * UGLD + c] = gl * a2;
}

// ---------------- attention: partial K^T Q (deterministic two-stage) ----------------
// grid (16 chunks, 6 heads, 8 batch), block 256; each thread owns 4 (c,d) entries.
__global__ void attn_partial(const float* __restrict__ qkv,
                             const float* __restrict__ mq, const float* __restrict__ vq,
                             const float* __restrict__ mk, const float* __restrict__ vk,
                             float* __restrict__ part) {
    int chunk = blockIdx.x, h = blockIdx.y, b = blockIdx.z;
    __shared__ __align__(16) float sq[8][32];
    __shared__ float sk[8][32];
    int tid = threadIdx.x;
    int c  = tid >> 3;            // (tid*4)>>5
    int d0 = (tid & 7) << 2;      // (tid*4)&31
    size_t rowbase = ((size_t)b * NPB + chunk * 1024) * C3;
    int hwbase = chunk * 1024;
    float acc0 = 0.f, acc1 = 0.f, acc2 = 0.f, acc3 = 0.f;

    for (int n0 = 0; n0 < 1024; n0 += 8) {
        int t = tid;
#pragma unroll
        for (int it = 0; it < 2; it++, t += 256) {
            int nn = t >> 6;
            int cc = t & 63;
            int nl = n0 + nn;
            int hw = hwbase + nl;
            size_t row = rowbase + (size_t)nl * C3;
            if (cc < 32) {
                sq[nn][cc] = (qkv[row + h * HD + cc] - mq[hw]) * rsqrtf(vq[hw]);
            } else {
                int k = cc - 32;
                sk[nn][k] = (qkv[row + CDIM + h * HD + k] - mk[hw]) * rsqrtf(vk[hw]);
            }
        }
        __syncthreads();
#pragma unroll
        for (int nn = 0; nn < 8; nn++) {
            float kv = sk[nn][c];
            float4 qv = *reinterpret_cast<const float4*>(&sq[nn][d0]);
            acc0 += kv * qv.x; acc1 += kv * qv.y; acc2 += kv * qv.z; acc3 += kv * qv.w;
        }
        __syncthreads();
    }
    float* o = part + (((size_t)(b * HEADS + h) * 16 + chunk) * 1024) + tid * 4;
    o[0] = acc0; o[1] = acc1; o[2] = acc2; o[3] = acc3;
}

// ---------------- reduce partials + temp + softmax over axis c ----------------
__global__ void softmax_kernel(const float* __restrict__ part, const float* __restrict__ temp,
                               float* __restrict__ attn) {
    int bh = blockIdx.x;            // 48
    int h = bh % HEADS;
    int d = threadIdx.x;            // 32
    float t = temp[h];
    float v[32];
#pragma unroll
    for (int c = 0; c < 32; c++) {
        float s = 0.f;
        for (int ch = 0; ch < 16; ch++)
            s += part[((size_t)bh * 16 + ch) * 1024 + c * 32 + d];
        v[c] = s * t;
    }
    float m = -1e30f;
#pragma unroll
    for (int c = 0; c < 32; c++) m = fmaxf(m, v[c]);
    float sum = 0.f;
#pragma unroll
    for (int c = 0; c < 32; c++) { v[c] = expf(v[c] - m); sum += v[c]; }
    float inv = 1.f / sum;
#pragma unroll
    for (int c = 0; c < 32; c++)
        attn[(size_t)bh * 1024 + c * 32 + d] = v[c] * inv;
}

// ---------------- fold attn into w_proj: W2[b][h*32+c][o] = sum_d attn[c][d] wproj[h*32+d][o]
__global__ void w2_kernel(const float* __restrict__ attn, const float* __restrict__ wproj,
                          float* __restrict__ W2) {
    int bh = blockIdx.x;            // 48
    int b = bh / HEADS, h = bh % HEADS;
    __shared__ float sA[32][32];
    __shared__ float sW[32][192];
    int tid = threadIdx.x;          // 192
    for (int t = tid; t < 1024; t += 192)
        sA[t >> 5][t & 31] = attn[(size_t)bh * 1024 + t];
    for (int dd = 0; dd < 32; dd++)
        sW[dd][tid] = wproj[(h * HD + dd) * CDIM + tid];
    __syncthreads();
    int o = tid;
    for (int c = 0; c < 32; c++) {
        float acc = 0.f;
#pragma unroll
        for (int dd = 0; dd < 32; dd++) acc += sA[c][dd] * sW[dd][o];
        W2[((size_t)b * CDIM + h * HD + c) * CDIM + o] = acc;
    }
}

// ---------------- launch ----------------
extern "C" void kernel_launch(void* const* d_in, const int* in_sizes, int n_in,
                              void* d_out, int out_size) {
    const float* x       = (const float*)d_in[0];
    const float* g1      = (const float*)d_in[1];
    const float* b1      = (const float*)d_in[2];
    const float* w_qkv   = (const float*)d_in[3];
    const float* w_qkv_dw= (const float*)d_in[4];
    const float* temp    = (const float*)d_in[5];
    const float* mean_q  = (const float*)d_in[6];
    const float* var_q   = (const float*)d_in[7];
    const float* mean_k  = (const float*)d_in[8];
    const float* var_k   = (const float*)d_in[9];
    const float* w_proj  = (const float*)d_in[10];
    const float* g2      = (const float*)d_in[11];
    const float* b2      = (const float*)d_in[12];
    const float* w_in    = (const float*)d_in[13];
    const float* w_ffn_dw= (const float*)d_in[14];
    const float* w_out   = (const float*)d_in[15];
    float* out = (float*)d_out;

    float *p_y, *p_qkvp, *p_qkv, *p_part, *p_attn, *p_W2, *p_x1, *p_upre, *p_ug;
    cudaGetSymbolAddress((void**)&p_y,    g_y);
    cudaGetSymbolAddress((void**)&p_qkvp, g_qkv_pre);
    cudaGetSymbolAddress((void**)&p_qkv,  g_qkv);
    cudaGetSymbolAddress((void**)&p_part, g_part);
    cudaGetSymbolAddress((void**)&p_attn, g_attn);
    cudaGetSymbolAddress((void**)&p_W2,   g_W2);
    cudaGetSymbolAddress((void**)&p_x1,   g_x1);
    cudaGetSymbolAddress((void**)&p_upre, g_upre);
    cudaGetSymbolAddress((void**)&p_ug,   g_ug);

    // 1. LN1
    ln_kernel<<<NPIX / 8, 256>>>(x, g1, b1, p_y);
    // 2. qkv = y @ w_qkv   [131072,192]x[192,576]
    gemm_kernel<<<dim3(C3 / 64, NPIX / 64, 1), 256>>>(p_y, CDIM, 0, w_qkv, 0, nullptr,
                                                      p_qkvp, NPIX, CDIM, C3);
    // 3. depthwise 3x3 on qkv
    dwconv_kernel<<<NPIX, C3>>>(p_qkvp, w_qkv_dw, p_qkv, C3);
    // 4. K^T Q partials (per batch/head, 16 n-chunks)
    attn_partial<<<dim3(16, HEADS, BATCH), 256>>>(p_qkv, mean_q, var_q, mean_k, var_k, p_part);
    // 5. reduce + temp + softmax(axis=-2)
    softmax_kernel<<<48, 32>>>(p_part, temp, p_attn);
    // 6. fold attn into w_proj (per batch effective 192x192 weight)
    w2_kernel<<<48, 192>>>(p_attn, w_proj, p_W2);
    // 7. x1 = x + V @ W2[b]   (batched GEMM, A = qkv cols 384..575)
    gemm_kernel<<<dim3(CDIM / 64, NPB / 64, BATCH), 256>>>(p_qkv, C3, 384, p_W2, CDIM * CDIM,
                                                           x, p_x1, NPB, CDIM, CDIM);
    // 8. LN2
    ln_kernel<<<NPIX / 8, 256>>>(p_x1, g2, b2, p_y);
    // 9. u_pre = y @ w_in   [131072,192]x[192,1020]
    gemm_kernel<<<dim3((HID2 + 63) / 64, NPIX / 64, 1), 256>>>(p_y, CDIM, 0, w_in, 0, nullptr,
                                                               p_upre, NPIX, CDIM, HID2);
    // 10. depthwise 3x3 + GELU gate fused -> ug [131072,510] (lda 512)
    dwconv_ffn_gate<<<NPIX, 512>>>(p_upre, w_ffn_dw, p_ug);
    // 11. out = x1 + ug @ w_out   [131072,510]x[510,192]
    gemm_kernel<<<dim3(CDIM / 64, NPIX / 64, 1), 256>>>(p_ug, UGLD, 0, w_out, 0, p_x1,
                                                        out, NPIX, HID, CDIM);
    (void)in_sizes; (void)n_in; (void)out_size;
}

// round 2
// speedup vs baseline: 1.6065x; 1.6065x over previous
#include <cuda_runtime.h>
#include <math.h>

// Problem constants
#define NPIX   131072      // B*H*W = 8*128*128
#define BATCH  8
#define HH     128
#define WW     128
#define CDIM   192
#define C3     576         // 3*CDIM
#define HEADS  6
#define HD     32          // head dim
#define HID    510
#define HID2   1020        // 2*HID
#define UGLD   512         // padded lda for gated ffn activation (cols 510,511 zeroed)
#define NPB    16384       // pixels per batch

// ---------------- scratch (device globals; allocation-free rule) ----------------
__device__ float g_y[(size_t)NPIX * CDIM];
__device__ float g_qkv_pre[(size_t)NPIX * C3];
__device__ float g_qkv[(size_t)NPIX * C3];
__device__ float g_part[48 * 16 * 1024];     // partial K^T Q sums, 16 chunks
__device__ float g_attn[48 * 1024];
__device__ float g_W2[BATCH * CDIM * CDIM];  // attn folded into w_proj, per batch
__device__ float g_x1[(size_t)NPIX * CDIM];
__device__ float g_upre[(size_t)NPIX * HID2];
__device__ float g_ug[(size_t)NPIX * UGLD];

// ---------------- helpers ----------------
__device__ __forceinline__ unsigned f2tf(float f) {
    unsigned u;
    asm("cvt.rna.tf32.f32 %0, %1;" : "=r"(u) : "f"(f));
    return u;
}

__device__ __forceinline__ void mma_tf32(float* d, unsigned a0, unsigned a1, unsigned a2,
                                         unsigned a3, unsigned b0, unsigned b1) {
    asm volatile(
        "mma.sync.aligned.m16n8k8.row.col.f32.tf32.tf32.f32 "
        "{%0,%1,%2,%3},{%4,%5,%6,%7},{%8,%9},{%0,%1,%2,%3};"
        : "+f"(d[0]), "+f"(d[1]), "+f"(d[2]), "+f"(d[3])
        : "r"(a0), "r"(a1), "r"(a2), "r"(a3), "r"(b0), "r"(b1));
}

// ---------------- LayerNorm (one warp per pixel, C=192 = 6 per lane) ----------------
__global__ void ln_kernel(const float* __restrict__ x, const float* __restrict__ g,
                          const float* __restrict__ b, float* __restrict__ y) {
    size_t warp = ((size_t)blockIdx.x * blockDim.x + threadIdx.x) >> 5;
    int lane = threadIdx.x & 31;
    const float* xr = x + warp * CDIM;
    float v[6]; float s = 0.f, s2 = 0.f;
#pragma unroll
    for (int i = 0; i < 6; i++) { v[i] = xr[lane + 32 * i]; s += v[i]; s2 += v[i] * v[i]; }
#pragma unroll
    for (int o = 16; o; o >>= 1) {
        s  += __shfl_xor_sync(0xffffffffu, s, o);
        s2 += __shfl_xor_sync(0xffffffffu, s2, o);
    }
    float mu  = s * (1.f / CDIM);
    float var = s2 * (1.f / CDIM) - mu * mu;
    float rs = rsqrtf(var + 1e-3f);
    float* yr = y + warp * CDIM;
#pragma unroll
    for (int i = 0; i < 6; i++) {
        int c = lane + 32 * i;
        yr[c] = (v[i] - mu) * rs * g[c] + b[c];
    }
}

// ---------------- TF32 tensor-core GEMM: C = A(:,aoff:aoff+K) * B (+R) ----------------
// Block tile 128x64, BK=16, 256 threads = 8 warps (4 over M, 2 over N), warp tile 32x32.
// Batched over blockIdx.z. Kpad: multiple of 16 (A readable up to Kpad); Kreal: true K
// (B rows >= Kreal are treated as zero; A cols in [Kreal,Kpad) must be zero in memory).
#define LDA_S 136
#define LDB_S 72
__global__ void __launch_bounds__(256) gemm_tc(
    const float* __restrict__ A, int lda, int aoff,
    const float* __restrict__ B, int bstride,
    const float* __restrict__ R,
    float* __restrict__ C,
    int Nper, int Kpad, int Kreal, int M)
{
    __shared__ unsigned As[16 * LDA_S];
    __shared__ unsigned Bs[16 * LDB_S];

    int bz = blockIdx.z;
    A += (size_t)bz * Nper * lda;
    B += (size_t)bz * bstride;
    if (R) R += (size_t)bz * (size_t)Nper * M;
    C += (size_t)bz * (size_t)Nper * M;

    int tid = threadIdx.x;
    int row0 = blockIdx.y * 128;
    int col0 = blockIdx.x * 64;
    int warp = tid >> 5, lane = tid & 31;
    int wm = warp & 3, wn = warp >> 2;
    int g = lane >> 2, tig = lane & 3;
    bool mfull = (col0 + 64 <= M);

    // A-load mapping: 2 float4 per thread covering 128 rows x 16 k
    int arow = tid >> 2;
    int ak4 = (tid & 3) << 2;
    // B-load mapping: 1 float4 per thread covering 16 k x 64 n
    int bkrow = tid >> 4;
    int bn4 = (tid & 15) << 2;

    float acc[2][4][4];
#pragma unroll
    for (int mt = 0; mt < 2; mt++)
#pragma unroll
        for (int nt = 0; nt < 4; nt++)
#pragma unroll
            for (int i = 0; i < 4; i++) acc[mt][nt][i] = 0.f;

    for (int k0 = 0; k0 < Kpad; k0 += 16) {
        // ---- stage A (transposed, cvt to tf32) ----
#pragma unroll
        for (int i = 0; i < 2; i++) {
            int row = arow + i * 64;
            const float4 v = *reinterpret_cast<const float4*>(
                A + (size_t)(row0 + row) * lda + aoff + k0 + ak4);
            As[(ak4 + 0) * LDA_S + row] = f2tf(v.x);
            As[(ak4 + 1) * LDA_S + row] = f2tf(v.y);
            As[(ak4 + 2) * LDA_S + row] = f2tf(v.z);
            As[(ak4 + 3) * LDA_S + row] = f2tf(v.w);
        }
        // ---- stage B ----
        {
            int kk = k0 + bkrow;
            if (mfull && kk < Kreal) {
                const float4 v = *reinterpret_cast<const float4*>(
                    B + (size_t)kk * M + col0 + bn4);
                Bs[bkrow * LDB_S + bn4 + 0] = f2tf(v.x);
                Bs[bkrow * LDB_S + bn4 + 1] = f2tf(v.y);
                Bs[bkrow * LDB_S + bn4 + 2] = f2tf(v.z);
                Bs[bkrow * LDB_S + bn4 + 3] = f2tf(v.w);
            } else {
#pragma unroll
                for (int j = 0; j < 4; j++) {
                    float val = (kk < Kreal && col0 + bn4 + j < M)
                                ? B[(size_t)kk * M + col0 + bn4 + j] : 0.f;
                    Bs[bkrow * LDB_S + bn4 + j] = f2tf(val);
                }
            }
        }
        __syncthreads();

#pragma unroll
        for (int ks = 0; ks < 2; ks++) {
            int k8 = ks * 8;
            unsigned bf[4][2];
#pragma unroll
            for (int nt = 0; nt < 4; nt++) {
                int cb = wn * 32 + nt * 8 + g;
                bf[nt][0] = Bs[(k8 + tig) * LDB_S + cb];
                bf[nt][1] = Bs[(k8 + tig + 4) * LDB_S + cb];
            }
#pragma unroll
            for (int mt = 0; mt < 2; mt++) {
                int r = wm * 32 + mt * 16 + g;
                unsigned a0 = As[(k8 + tig) * LDA_S + r];
                unsigned a1 = As[(k8 + tig) * LDA_S + r + 8];
                unsigned a2 = As[(k8 + tig + 4) * LDA_S + r];
                unsigned a3 = As[(k8 + tig + 4) * LDA_S + r + 8];
#pragma unroll
                for (int nt = 0; nt < 4; nt++)
                    mma_tf32(acc[mt][nt], a0, a1, a2, a3, bf[nt][0], bf[nt][1]);
            }
        }
        __syncthreads();
    }

    // ---- epilogue ----
#pragma unroll
    for (int mt = 0; mt < 2; mt++) {
        size_t r = (size_t)row0 + wm * 32 + mt * 16 + g;
#pragma unroll
        for (int nt = 0; nt < 4; nt++) {
            int col = col0 + wn * 32 + nt * 8 + tig * 2;
            float* p0 = C + r * M + col;
            float* p1 = C + (r + 8) * M + col;
            if (mfull) {
                float2 o0 = make_float2(acc[mt][nt][0], acc[mt][nt][1]);
                float2 o1 = make_float2(acc[mt][nt][2], acc[mt][nt][3]);
                if (R) {
                    float2 r0 = *reinterpret_cast<const float2*>(R + r * M + col);
                    float2 r1 = *reinterpret_cast<const float2*>(R + (r + 8) * M + col);
                    o0.x += r0.x; o0.y += r0.y; o1.x += r1.x; o1.y += r1.y;
                }
                *reinterpret_cast<float2*>(p0) = o0;
                *reinterpret_cast<float2*>(p1) = o1;
            } else if (col < M) {  // M always even; col even => col+1 < M too
                float o0 = acc[mt][nt][0], o1 = acc[mt][nt][1];
                float o2 = acc[mt][nt][2], o3 = acc[mt][nt][3];
                if (R) {
                    o0 += R[r * M + col]; o1 += R[r * M + col + 1];
                    o2 += R[(r + 8) * M + col]; o3 += R[(r + 8) * M + col + 1];
                }
                p0[0] = o0; p0[1] = o1; p1[0] = o2; p1[1] = o3;
            }
        }
    }
}

// ---------------- depthwise 3x3 SAME conv, NHWC, one block per pixel ----------------
__global__ void dwconv_kernel(const float* __restrict__ in, const float* __restrict__ w,
                              float* __restrict__ out, int C) {
    int p = blockIdx.x;
    int c = threadIdx.x;
    int b = p >> 14, hw = p & 16383, yy = hw >> 7, xx = hw & 127;
    float acc = 0.f;
#pragma unroll
    for (int ky = -1; ky <= 1; ky++) {
        int yn = yy + ky;
        if ((unsigned)yn >= HH) continue;
#pragma unroll
        for (int kx = -1; kx <= 1; kx++) {
            int xn = xx + kx;
            if ((unsigned)xn >= WW) continue;
            size_t idx = ((size_t)(b << 14) + (yn << 7) + xn) * C + c;
            acc += in[idx] * w[((ky + 1) * 3 + (kx + 1)) * C + c];
        }
    }
    out[(size_t)p * C + c] = acc;
}

// ---------------- FFN depthwise 3x3 + exact-GELU gating fused ----------------
__global__ void dwconv_ffn_gate(const float* __restrict__ in, const float* __restrict__ w,
                                float* __restrict__ out) {
    int p = blockIdx.x;
    int c = threadIdx.x;          // blockDim = 512
    if (c >= HID) {               // zero-pad cols 510,511 so Kpad=512 GEMM reads zeros
        out[(size_t)p * UGLD + c] = 0.f;
        return;
    }
    int b = p >> 14, hw = p & 16383, yy = hw >> 7, xx = hw & 127;
    float a1 = 0.f, a2 = 0.f;
#pragma unroll
    for (int ky = -1; ky <= 1; ky++) {
        int yn = yy + ky;
        if ((unsigned)yn >= HH) continue;
#pragma unroll
        for (int kx = -1; kx <= 1; kx++) {
            int xn = xx + kx;
            if ((unsigned)xn >= WW) continue;
            size_t idx = ((size_t)(b << 14) + (yn << 7) + xn) * HID2;
            int wi = ((ky + 1) * 3 + (kx + 1)) * HID2;
            a1 += in[idx + c]        * w[wi + c];
            a2 += in[idx + HID + c]  * w[wi + HID + c];
        }
    }
    float gl = 0.5f * a1 * (1.f + erff(a1 * 0.70710678118654752f));
    out[(size_t)p * UGLD + c] = gl * a2;
}

// ---------------- attention: partial K^T Q (deterministic two-stage) ----------------
__global__ void attn_partial(const float* __restrict__ qkv,
                             const float* __restrict__ mq, const float* __restrict__ vq,
                             const float* __restrict__ mk, const float* __restrict__ vk,
                             float* __restrict__ part) {
    int chunk = blockIdx.x, h = blockIdx.y, b = blockIdx.z;
    __shared__ __align__(16) float sq[8][32];
    __shared__ float sk[8][32];
    int tid = threadIdx.x;
    int c  = tid >> 3;
    int d0 = (tid & 7) << 2;
    size_t rowbase = ((size_t)b * NPB + chunk * 1024) * C3;
    int hwbase = chunk * 1024;
    float acc0 = 0.f, acc1 = 0.f, acc2 = 0.f, acc3 = 0.f;

    for (int n0 = 0; n0 < 1024; n0 += 8) {
        int t = tid;
#pragma unroll
        for (int it = 0; it < 2; it++, t += 256) {
            int nn = t >> 6;
            int cc = t & 63;
            int nl = n0 + nn;
            int hw = hwbase + nl;
            size_t row = rowbase + (size_t)nl * C3;
            if (cc < 32) {
                sq[nn][cc] = (qkv[row + h * HD + cc] - mq[hw]) * rsqrtf(vq[hw]);
            } else {
                int k = cc - 32;
                sk[nn][k] = (qkv[row + CDIM + h * HD + k] - mk[hw]) * rsqrtf(vk[hw]);
            }
        }
        __syncthreads();
#pragma unroll
        for (int nn = 0; nn < 8; nn++) {
            float kv = sk[nn][c];
            float4 qv = *reinterpret_cast<const float4*>(&sq[nn][d0]);
            acc0 += kv * qv.x; acc1 += kv * qv.y; acc2 += kv * qv.z; acc3 += kv * qv.w;
        }
        __syncthreads();
    }
    float* o = part + (((size_t)(b * HEADS + h) * 16 + chunk) * 1024) + tid * 4;
    o[0] = acc0; o[1] = acc1; o[2] = acc2; o[3] = acc3;
}

// ---------------- reduce partials + temp + softmax over axis c ----------------
__global__ void softmax_kernel(const float* __restrict__ part, const float* __restrict__ temp,
                               float* __restrict__ attn) {
    int bh = blockIdx.x;            // 48
    int h = bh % HEADS;
    int d = threadIdx.x;            // 32
    float t = temp[h];
    float v[32];
#pragma unroll
    for (int c = 0; c < 32; c++) {
        float s = 0.f;
        for (int ch = 0; ch < 16; ch++)
            s += part[((size_t)bh * 16 + ch) * 1024 + c * 32 + d];
        v[c] = s * t;
    }
    float m = -1e30f;
#pragma unroll
    for (int c = 0; c < 32; c++) m = fmaxf(m, v[c]);
    float sum = 0.f;
#pragma unroll
    for (int c = 0; c < 32; c++) { v[c] = expf(v[c] - m); sum += v[c]; }
    float inv = 1.f / sum;
#pragma unroll
    for (int c = 0; c < 32; c++)
        attn[(size_t)bh * 1024 + c * 32 + d] = v[c] * inv;
}

// ---------------- fold attn into w_proj ----------------
__global__ void w2_kernel(const float* __restrict__ attn, const float* __restrict__ wproj,
                          float* __restrict__ W2) {
    int bh = blockIdx.x;            // 48
    int b = bh / HEADS, h = bh % HEADS;
    __shared__ float sA[32][32];
    __shared__ float sW[32][192];
    int tid = threadIdx.x;          // 192
    for (int t = tid; t < 1024; t += 192)
        sA[t >> 5][t & 31] = attn[(size_t)bh * 1024 + t];
    for (int dd = 0; dd < 32; dd++)
        sW[dd][tid] = wproj[(h * HD + dd) * CDIM + tid];
    __syncthreads();
    int o = tid;
    for (int c = 0; c < 32; c++) {
        float acc = 0.f;
#pragma unroll
        for (int dd = 0; dd < 32; dd++) acc += sA[c][dd] * sW[dd][o];
        W2[((size_t)b * CDIM + h * HD + c) * CDIM + o] = acc;
    }
}

// ---------------- launch ----------------
extern "C" void kernel_launch(void* const* d_in, const int* in_sizes, int n_in,
                              void* d_out, int out_size) {
    const float* x       = (const float*)d_in[0];
    const float* g1      = (const float*)d_in[1];
    const float* b1      = (const float*)d_in[2];
    const float* w_qkv   = (const float*)d_in[3];
    const float* w_qkv_dw= (const float*)d_in[4];
    const float* temp    = (const float*)d_in[5];
    const float* mean_q  = (const float*)d_in[6];
    const float* var_q   = (const float*)d_in[7];
    const float* mean_k  = (const float*)d_in[8];
    const float* var_k   = (const float*)d_in[9];
    const float* w_proj  = (const float*)d_in[10];
    const float* g2      = (const float*)d_in[11];
    const float* b2      = (const float*)d_in[12];
    const float* w_in    = (const float*)d_in[13];
    const float* w_ffn_dw= (const float*)d_in[14];
    const float* w_out   = (const float*)d_in[15];
    float* out = (float*)d_out;

    float *p_y, *p_qkvp, *p_qkv, *p_part, *p_attn, *p_W2, *p_x1, *p_upre, *p_ug;
    cudaGetSymbolAddress((void**)&p_y,    g_y);
    cudaGetSymbolAddress((void**)&p_qkvp, g_qkv_pre);
    cudaGetSymbolAddress((void**)&p_qkv,  g_qkv);
    cudaGetSymbolAddress((void**)&p_part, g_part);
    cudaGetSymbolAddress((void**)&p_attn, g_attn);
    cudaGetSymbolAddress((void**)&p_W2,   g_W2);
    cudaGetSymbolAddress((void**)&p_x1,   g_x1);
    cudaGetSymbolAddress((void**)&p_upre, g_upre);
    cudaGetSymbolAddress((void**)&p_ug,   g_ug);

    // 1. LN1
    ln_kernel<<<NPIX / 8, 256>>>(x, g1, b1, p_y);
    // 2. qkv = y @ w_qkv   [131072,192]x[192,576]
    gemm_tc<<<dim3(C3 / 64, NPIX / 128, 1), 256>>>(p_y, CDIM, 0, w_qkv, 0, nullptr,
                                                   p_qkvp, NPIX, CDIM, CDIM, C3);
    // 3. depthwise 3x3 on qkv
    dwconv_kernel<<<NPIX, C3>>>(p_qkvp, w_qkv_dw, p_qkv, C3);
    // 4. K^T Q partials
    attn_partial<<<dim3(16, HEADS, BATCH), 256>>>(p_qkv, mean_q, var_q, mean_k, var_k, p_part);
    // 5. reduce + temp + softmax(axis=-2)
    softmax_kernel<<<48, 32>>>(p_part, temp, p_attn);
    // 6. fold attn into w_proj
    w2_kernel<<<48, 192>>>(p_attn, w_proj, p_W2);
    // 7. x1 = x + V @ W2[b]   (batched, A = qkv cols 384..575)
    gemm_tc<<<dim3(CDIM / 64, NPB / 128, BATCH), 256>>>(p_qkv, C3, 384, p_W2, CDIM * CDIM,
                                                        x, p_x1, NPB, CDIM, CDIM, CDIM);
    // 8. LN2
    ln_kernel<<<NPIX / 8, 256>>>(p_x1, g2, b2, p_y);
    // 9. u_pre = y @ w_in   [131072,192]x[192,1020]
    gemm_tc<<<dim3((HID2 + 63) / 64, NPIX / 128, 1), 256>>>(p_y, CDIM, 0, w_in, 0, nullptr,
                                                            p_upre, NPIX, CDIM, CDIM, HID2);
    // 10. depthwise 3x3 + GELU gate fused -> ug [131072,510] (lda 512, zero-padded)
    dwconv_ffn_gate<<<NPIX, 512>>>(p_upre, w_ffn_dw, p_ug);
    // 11. out = x1 + ug @ w_out   [131072,510(pad512)]x[510,192]
    gemm_tc<<<dim3(CDIM / 64, NPIX / 128, 1), 256>>>(p_ug, UGLD, 0, w_out, 0, p_x1,
                                                     out, NPIX, UGLD, HID, CDIM);
    (void)in_sizes; (void)n_in; (void)out_size;
}

// round 3
// speedup vs baseline: 2.1055x; 1.3106x over previous
#include <cuda_runtime.h>
#include <cuda_bf16.h>
#include <math.h>

// Problem constants
#define NPIX   131072      // B*H*W = 8*128*128
#define BATCH  8
#define HH     128
#define WW     128
#define CDIM   192
#define C3     576         // 3*CDIM
#define HEADS  6
#define HD     32          // head dim
#define HID    510
#define HID2   1020        // 2*HID
#define UGLD   512         // padded lda for gated ffn activation (cols 510,511 zeroed)
#define NPB    16384       // pixels per batch

// ---------------- scratch (device globals; allocation-free rule) ----------------
__device__ float g_y[(size_t)NPIX * CDIM];
__device__ float g_qkv_pre[(size_t)NPIX * C3];
__device__ float g_qkv[(size_t)NPIX * C3];
__device__ float g_part[48 * 16 * 1024];     // partial K^T Q sums, 16 chunks
__device__ float g_attn[48 * 1024];
__device__ float g_W2[BATCH * CDIM * CDIM];  // attn folded into w_proj, per batch
__device__ float g_x1[(size_t)NPIX * CDIM];
__device__ float g_upre[(size_t)NPIX * HID2];
__device__ float g_ug[(size_t)NPIX * UGLD];

// ---------------- mma / ldmatrix helpers ----------------
__device__ __forceinline__ void ldsm4(unsigned* r, unsigned addr) {
    asm volatile("ldmatrix.sync.aligned.m8n8.x4.shared.b16 {%0,%1,%2,%3}, [%4];"
                 : "=r"(r[0]), "=r"(r[1]), "=r"(r[2]), "=r"(r[3]) : "r"(addr));
}
__device__ __forceinline__ void ldsm4t(unsigned* r, unsigned addr) {
    asm volatile("ldmatrix.sync.aligned.m8n8.x4.trans.shared.b16 {%0,%1,%2,%3}, [%4];"
                 : "=r"(r[0]), "=r"(r[1]), "=r"(r[2]), "=r"(r[3]) : "r"(addr));
}
__device__ __forceinline__ void mma_bf16(float* d, const unsigned* a, unsigned b0, unsigned b1) {
    asm volatile(
        "mma.sync.aligned.m16n8k16.row.col.f32.bf16.bf16.f32 "
        "{%0,%1,%2,%3},{%4,%5,%6,%7},{%8,%9},{%0,%1,%2,%3};"
        : "+f"(d[0]), "+f"(d[1]), "+f"(d[2]), "+f"(d[3])
        : "r"(a[0]), "r"(a[1]), "r"(a[2]), "r"(a[3]), "r"(b0), "r"(b1));
}

// ---------------- LayerNorm (one warp per pixel, C=192 = 6 per lane) ----------------
__global__ void ln_kernel(const float* __restrict__ x, const float* __restrict__ g,
                          const float* __restrict__ b, float* __restrict__ y) {
    size_t warp = ((size_t)blockIdx.x * blockDim.x + threadIdx.x) >> 5;
    int lane = threadIdx.x & 31;
    const float* xr = x + warp * CDIM;
    float v[6]; float s = 0.f, s2 = 0.f;
#pragma unroll
    for (int i = 0; i < 6; i++) { v[i] = xr[lane + 32 * i]; s += v[i]; s2 += v[i] * v[i]; }
#pragma unroll
    for (int o = 16; o; o >>= 1) {
        s  += __shfl_xor_sync(0xffffffffu, s, o);
        s2 += __shfl_xor_sync(0xffffffffu, s2, o);
    }
    float mu  = s * (1.f / CDIM);
    float var = s2 * (1.f / CDIM) - mu * mu;
    float rs = rsqrtf(var + 1e-3f);
    float* yr = y + warp * CDIM;
#pragma unroll
    for (int i = 0; i < 6; i++) {
        int c = lane + 32 * i;
        yr[c] = (v[i] - mu) * rs * g[c] + b[c];
    }
}

// ---------------- bf16 tensor-core GEMM: C = A(:,aoff:aoff+K) * B (+R) ----------------
// Block tile 128x64, BK=32, 256 threads = 8 warps (4 over M x 2 over N), warp tile 32x32.
// Double-buffered smem, ldmatrix fragments, mma.m16n8k16 bf16, fp32 accumulate.
#define LDAK 40     // bf16 pitch for As rows  (conflict-free ldmatrix: 80B -> 20-bank shift)
#define LDBN 72     // bf16 pitch for Bs rows  (144B -> 4-bank shift)
#define ASZ  (128 * LDAK)
#define BSZ  (32 * LDBN)
__global__ void __launch_bounds__(256) gemm_bf16(
    const float* __restrict__ A, int lda, int aoff,
    const float* __restrict__ B, int bstride,
    const float* __restrict__ R,
    float* __restrict__ C,
    int Nper, int Kpad, int Kreal, int M)
{
    __shared__ __nv_bfloat16 As[2 * ASZ];
    __shared__ __nv_bfloat16 Bs[2 * BSZ];

    int bz = blockIdx.z;
    A += (size_t)bz * Nper * lda;
    B += (size_t)bz * bstride;
    if (R) R += (size_t)bz * (size_t)Nper * M;
    C += (size_t)bz * (size_t)Nper * M;

    int tid = threadIdx.x;
    int row0 = blockIdx.y * 128;
    int col0 = blockIdx.x * 64;
    int warp = tid >> 5, lane = tid & 31;
    int wm = warp & 3, wn = warp >> 2;
    int g = lane >> 2, tig = lane & 3;
    bool mfull = (col0 + 64 <= M);

    unsigned as_base = (unsigned)__cvta_generic_to_shared(As);
    unsigned bs_base = (unsigned)__cvta_generic_to_shared(Bs);

    float4 fa[4];
    float4 fb[2];

    float acc[2][4][4];
#pragma unroll
    for (int mt = 0; mt < 2; mt++)
#pragma unroll
        for (int nt = 0; nt < 4; nt++)
#pragma unroll
            for (int i = 0; i < 4; i++) acc[mt][nt][i] = 0.f;

    // ---- loaders ----
    auto load_regs = [&](int k0) {
#pragma unroll
        for (int i = 0; i < 4; i++) {
            int id = tid + i * 256;
            int row = id >> 3;
            int kq = (id & 7) << 2;
            fa[i] = *reinterpret_cast<const float4*>(
                A + (size_t)(row0 + row) * lda + aoff + k0 + kq);
        }
#pragma unroll
        for (int i = 0; i < 2; i++) {
            int id = tid + i * 256;
            int kr = id >> 4;
            int nq = (id & 15) << 2;
            int kk = k0 + kr;
            if (mfull && kk < Kreal) {
                fb[i] = *reinterpret_cast<const float4*>(B + (size_t)kk * M + col0 + nq);
            } else {
                float4 v = make_float4(0.f, 0.f, 0.f, 0.f);
                if (kk < Kreal) {
                    const float* p = B + (size_t)kk * M;
                    if (col0 + nq + 0 < M) v.x = p[col0 + nq + 0];
                    if (col0 + nq + 1 < M) v.y = p[col0 + nq + 1];
                    if (col0 + nq + 2 < M) v.z = p[col0 + nq + 2];
                    if (col0 + nq + 3 < M) v.w = p[col0 + nq + 3];
                }
                fb[i] = v;
            }
        }
    };
    auto store_smem = [&](int buf) {
        __nv_bfloat16* as = As + buf * ASZ;
        __nv_bfloat16* bs = Bs + buf * BSZ;
#pragma unroll
        for (int i = 0; i < 4; i++) {
            int id = tid + i * 256;
            int row = id >> 3;
            int kq = (id & 7) << 2;
            __nv_bfloat162 p0 = __floats2bfloat162_rn(fa[i].x, fa[i].y);
            __nv_bfloat162 p1 = __floats2bfloat162_rn(fa[i].z, fa[i].w);
            *reinterpret_cast<__nv_bfloat162*>(as + row * LDAK + kq)     = p0;
            *reinterpret_cast<__nv_bfloat162*>(as + row * LDAK + kq + 2) = p1;
        }
#pragma unroll
        for (int i = 0; i < 2; i++) {
            int id = tid + i * 256;
            int kr = id >> 4;
            int nq = (id & 15) << 2;
            __nv_bfloat162 p0 = __floats2bfloat162_rn(fb[i].x, fb[i].y);
            __nv_bfloat162 p1 = __floats2bfloat162_rn(fb[i].z, fb[i].w);
            *reinterpret_cast<__nv_bfloat162*>(bs + kr * LDBN + nq)     = p0;
            *reinterpret_cast<__nv_bfloat162*>(bs + kr * LDBN + nq + 2) = p1;
        }
    };
    auto compute = [&](int buf) {
        unsigned abase = as_base + buf * (ASZ * 2);
        unsigned bbase = bs_base + buf * (BSZ * 2);
        int lrow = lane & 15, lhi = lane >> 4;
#pragma unroll
        for (int ks = 0; ks < 2; ks++) {
            unsigned afr[2][4];
#pragma unroll
            for (int mt = 0; mt < 2; mt++) {
                unsigned addr = abase +
                    ((wm * 32 + mt * 16 + lrow) * LDAK + ks * 16 + lhi * 8) * 2;
                ldsm4(afr[mt], addr);
            }
            unsigned bfr[2][4];
#pragma unroll
            for (int np = 0; np < 2; np++) {
                unsigned addr = bbase +
                    ((ks * 16 + lrow) * LDBN + wn * 32 + np * 16 + lhi * 8) * 2;
                ldsm4t(bfr[np], addr);
            }
#pragma unroll
            for (int mt = 0; mt < 2; mt++)
#pragma unroll
                for (int np = 0; np < 2; np++) {
                    mma_bf16(acc[mt][np * 2 + 0], afr[mt], bfr[np][0], bfr[np][1]);
                    mma_bf16(acc[mt][np * 2 + 1], afr[mt], bfr[np][2], bfr[np][3]);
                }
        }
    };

    // ---- pipelined mainloop ----
    load_regs(0);
    store_smem(0);
    __syncthreads();
    int buf = 0;
    for (int k0 = 0; k0 < Kpad; k0 += 32) {
        bool has_next = (k0 + 32 < Kpad);
        if (has_next) load_regs(k0 + 32);
        compute(buf);
        if (has_next) {
            store_smem(buf ^ 1);
            __syncthreads();
            buf ^= 1;
        }
    }

    // ---- epilogue ----
#pragma unroll
    for (int mt = 0; mt < 2; mt++) {
        size_t r = (size_t)row0 + wm * 32 + mt * 16 + g;
#pragma unroll
        for (int nt = 0; nt < 4; nt++) {
            int col = col0 + wn * 32 + nt * 8 + tig * 2;
            float* p0 = C + r * M + col;
            float* p1 = C + (r + 8) * M + col;
            if (mfull) {
                float2 o0 = make_float2(acc[mt][nt][0], acc[mt][nt][1]);
                float2 o1 = make_float2(acc[mt][nt][2], acc[mt][nt][3]);
                if (R) {
                    float2 r0 = *reinterpret_cast<const float2*>(R + r * M + col);
                    float2 r1 = *reinterpret_cast<const float2*>(R + (r + 8) * M + col);
                    o0.x += r0.x; o0.y += r0.y; o1.x += r1.x; o1.y += r1.y;
                }
                *reinterpret_cast<float2*>(p0) = o0;
                *reinterpret_cast<float2*>(p1) = o1;
            } else if (col < M) {  // M even; col even => col+1 < M too
                float o0 = acc[mt][nt][0], o1 = acc[mt][nt][1];
                float o2 = acc[mt][nt][2], o3 = acc[mt][nt][3];
                if (R) {
                    o0 += R[r * M + col]; o1 += R[r * M + col + 1];
                    o2 += R[(r + 8) * M + col]; o3 += R[(r + 8) * M + col + 1];
                }
                p0[0] = o0; p0[1] = o1; p1[0] = o2; p1[1] = o3;
            }
        }
    }
}

// ---------------- depthwise 3x3 SAME conv, NHWC, one block per pixel ----------------
__global__ void dwconv_kernel(const float* __restrict__ in, const float* __restrict__ w,
                              float* __restrict__ out, int C) {
    int p = blockIdx.x;
    int c = threadIdx.x;
    int b = p >> 14, hw = p & 16383, yy = hw >> 7, xx = hw & 127;
    float acc = 0.f;
#pragma unroll
    for (int ky = -1; ky <= 1; ky++) {
        int yn = yy + ky;
        if ((unsigned)yn >= HH) continue;
#pragma unroll
        for (int kx = -1; kx <= 1; kx++) {
            int xn = xx + kx;
            if ((unsigned)xn >= WW) continue;
            size_t idx = ((size_t)(b << 14) + (yn << 7) + xn) * C + c;
            acc += in[idx] * w[((ky + 1) * 3 + (kx + 1)) * C + c];
        }
    }
    out[(size_t)p * C + c] = acc;
}

// ---------------- FFN depthwise 3x3 + exact-GELU gating fused ----------------
__global__ void dwconv_ffn_gate(const float* __restrict__ in, const float* __restrict__ w,
                                float* __restrict__ out) {
    int p = blockIdx.x;
    int c = threadIdx.x;          // blockDim = 512
    if (c >= HID) {               // zero-pad cols 510,511 so Kpad=512 GEMM reads zeros
        out[(size_t)p * UGLD + c] = 0.f;
        return;
    }
    int b = p >> 14, hw = p & 16383, yy = hw >> 7, xx = hw & 127;
    float a1 = 0.f, a2 = 0.f;
#pragma unroll
    for (int ky = -1; ky <= 1; ky++) {
        int yn = yy + ky;
        if ((unsigned)yn >= HH) continue;
#pragma unroll
        for (int kx = -1; kx <= 1; kx++) {
            int xn = xx + kx;
            if ((unsigned)xn >= WW) continue;
            size_t idx = ((size_t)(b << 14) + (yn << 7) + xn) * HID2;
            int wi = ((ky + 1) * 3 + (kx + 1)) * HID2;
            a1 += in[idx + c]        * w[wi + c];
            a2 += in[idx + HID + c]  * w[wi + HID + c];
        }
    }
    float gl = 0.5f * a1 * (1.f + erff(a1 * 0.70710678118654752f));
    out[(size_t)p * UGLD + c] = gl * a2;
}

// ---------------- attention: partial K^T Q (deterministic two-stage) ----------------
// v2: per-pixel scale hoist (rsqrtf once per pixel), float4 staging, 16 rows/stage.
__global__ void __launch_bounds__(256) attn_partial(
        const float* __restrict__ qkv,
        const float* __restrict__ mq, const float* __restrict__ vq,
        const float* __restrict__ mk, const float* __restrict__ vk,
        float* __restrict__ part) {
    int chunk = blockIdx.x, h = blockIdx.y, b = blockIdx.z;
    __shared__ __align__(16) float sq[16][32];
    __shared__ float sk[16][32];
    __shared__ float sm[2][16];   // mq, mk
    __shared__ float sr[2][16];   // rsqrt(vq), rsqrt(vk)
    int tid = threadIdx.x;
    int c  = tid >> 3;
    int d0 = (tid & 7) << 2;
    size_t rowbase = ((size_t)b * NPB + chunk * 1024) * C3;
    int hwbase = chunk * 1024;
    int nn_l = tid >> 4;          // 0..15 (staging row)
    int prt  = tid & 15;          // 0..15 (staging slot)
    float acc0 = 0.f, acc1 = 0.f, acc2 = 0.f, acc3 = 0.f;

    for (int n0 = 0; n0 < 1024; n0 += 16) {
        // phase A: per-pixel scales (32 threads)
        if (tid < 32) {
            int qk = tid >> 4;          // 0=q, 1=k
            int nn = tid & 15;
            int hw = hwbase + n0 + nn;
            if (qk == 0) { sm[0][nn] = mq[hw]; sr[0][nn] = rsqrtf(vq[hw]); }
            else         { sm[1][nn] = mk[hw]; sr[1][nn] = rsqrtf(vk[hw]); }
        }
        __syncthreads();
        // phase B: stage 16 rows of q,k (float4 per thread)
        {
            size_t row = rowbase + (size_t)(n0 + nn_l) * C3;
            if (prt < 8) {
                float4 v = *reinterpret_cast<const float4*>(&qkv[row + h * HD + prt * 4]);
                float m = sm[0][nn_l], rs = sr[0][nn_l];
                float* d = &sq[nn_l][prt * 4];
                d[0] = (v.x - m) * rs; d[1] = (v.y - m) * rs;
                d[2] = (v.z - m) * rs; d[3] = (v.w - m) * rs;
            } else {
                float4 v = *reinterpret_cast<const float4*>(
                    &qkv[row + CDIM + h * HD + (prt - 8) * 4]);
                float m = sm[1][nn_l], rs = sr[1][nn_l];
                float* d = &sk[nn_l][(prt - 8) * 4];
                d[0] = (v.x - m) * rs; d[1] = (v.y - m) * rs;
                d[2] = (v.z - m) * rs; d[3] = (v.w - m) * rs;
            }
        }
        __syncthreads();
        // phase C: accumulate outer products
#pragma unroll
        for (int nn = 0; nn < 16; nn++) {
            float kv = sk[nn][c];
            float4 qv = *reinterpret_cast<const float4*>(&sq[nn][d0]);
            acc0 += kv * qv.x; acc1 += kv * qv.y; acc2 += kv * qv.z; acc3 += kv * qv.w;
        }
        __syncthreads();
    }
    float* o = part + (((size_t)(b * HEADS + h) * 16 + chunk) * 1024) + tid * 4;
    o[0] = acc0; o[1] = acc1; o[2] = acc2; o[3] = acc3;
}

// ---------------- reduce partials + temp + softmax over axis c ----------------
__global__ void softmax_kernel(const float* __restrict__ part, const float* __restrict__ temp,
                               float* __restrict__ attn) {
    int bh = blockIdx.x;            // 48
    int h = bh % HEADS;
    int d = threadIdx.x;            // 32
    float t = temp[h];
    float v[32];
#pragma unroll
    for (int c = 0; c < 32; c++) {
        float s = 0.f;
        for (int ch = 0; ch < 16; ch++)
            s += part[((size_t)bh * 16 + ch) * 1024 + c * 32 + d];
        v[c] = s * t;
    }
    float m = -1e30f;
#pragma unroll
    for (int c = 0; c < 32; c++) m = fmaxf(m, v[c]);
    float sum = 0.f;
#pragma unroll
    for (int c = 0; c < 32; c++) { v[c] = expf(v[c] - m); sum += v[c]; }
    float inv = 1.f / sum;
#pragma unroll
    for (int c = 0; c < 32; c++)
        attn[(size_t)bh * 1024 + c * 32 + d] = v[c] * inv;
}

// ---------------- fold attn into w_proj ----------------
__global__ void w2_kernel(const float* __restrict__ attn, const float* __restrict__ wproj,
                          float* __restrict__ W2) {
    int bh = blockIdx.x;            // 48
    int b = bh / HEADS, h = bh % HEADS;
    __shared__ float sA[32][32];
    __shared__ float sW[32][192];
    int tid = threadIdx.x;          // 192
    for (int t = tid; t < 1024; t += 192)
        sA[t >> 5][t & 31] = attn[(size_t)bh * 1024 + t];
    for (int dd = 0; dd < 32; dd++)
        sW[dd][tid] = wproj[(h * HD + dd) * CDIM + tid];
    __syncthreads();
    int o = tid;
    for (int c = 0; c < 32; c++) {
        float acc = 0.f;
#pragma unroll
        for (int dd = 0; dd < 32; dd++) acc += sA[c][dd] * sW[dd][o];
        W2[((size_t)b * CDIM + h * HD + c) * CDIM + o] = acc;
    }
}

// ---------------- launch ----------------
extern "C" void kernel_launch(void* const* d_in, const int* in_sizes, int n_in,
                              void* d_out, int out_size) {
    const float* x       = (const float*)d_in[0];
    const float* g1      = (const float*)d_in[1];
    const float* b1      = (const float*)d_in[2];
    const float* w_qkv   = (const float*)d_in[3];
    const float* w_qkv_dw= (const float*)d_in[4];
    const float* temp    = (const float*)d_in[5];
    const float* mean_q  = (const float*)d_in[6];
    const float* var_q   = (const float*)d_in[7];
    const float* mean_k  = (const float*)d_in[8];
    const float* var_k   = (const float*)d_in[9];
    const float* w_proj  = (const float*)d_in[10];
    const float* g2      = (const float*)d_in[11];
    const float* b2      = (const float*)d_in[12];
    const float* w_in    = (const float*)d_in[13];
    const float* w_ffn_dw= (const float*)d_in[14];
    const float* w_out   = (const float*)d_in[15];
    float* out = (float*)d_out;

    float *p_y, *p_qkvp, *p_qkv, *p_part, *p_attn, *p_W2, *p_x1, *p_upre, *p_ug;
    cudaGetSymbolAddress((void**)&p_y,    g_y);
    cudaGetSymbolAddress((void**)&p_qkvp, g_qkv_pre);
    cudaGetSymbolAddress((void**)&p_qkv,  g_qkv);
    cudaGetSymbolAddress((void**)&p_part, g_part);
    cudaGetSymbolAddress((void**)&p_attn, g_attn);
    cudaGetSymbolAddress((void**)&p_W2,   g_W2);
    cudaGetSymbolAddress((void**)&p_x1,   g_x1);
    cudaGetSymbolAddress((void**)&p_upre, g_upre);
    cudaGetSymbolAddress((void**)&p_ug,   g_ug);

    // 1. LN1
    ln_kernel<<<NPIX / 8, 256>>>(x, g1, b1, p_y);
    // 2. qkv = y @ w_qkv   [131072,192]x[192,576]
    gemm_bf16<<<dim3(C3 / 64, NPIX / 128, 1), 256>>>(p_y, CDIM, 0, w_qkv, 0, nullptr,
                                                     p_qkvp, NPIX, CDIM, CDIM, C3);
    // 3. depthwise 3x3 on qkv
    dwconv_kernel<<<NPIX, C3>>>(p_qkvp, w_qkv_dw, p_qkv, C3);
    // 4. K^T Q partials
    attn_partial<<<dim3(16, HEADS, BATCH), 256>>>(p_qkv, mean_q, var_q, mean_k, var_k, p_part);
    // 5. reduce + temp + softmax(axis=-2)
    softmax_kernel<<<48, 32>>>(p_part, temp, p_attn);
    // 6. fold attn into w_proj
    w2_kernel<<<48, 192>>>(p_attn, w_proj, p_W2);
    // 7. x1 = x + V @ W2[b]   (batched, A = qkv cols 384..575)
    gemm_bf16<<<dim3(CDIM / 64, NPB / 128, BATCH), 256>>>(p_qkv, C3, 384, p_W2, CDIM * CDIM,
                                                          x, p_x1, NPB, CDIM, CDIM, CDIM);
    // 8. LN2
    ln_kernel<<<NPIX / 8, 256>>>(p_x1, g2, b2, p_y);
    // 9. u_pre = y @ w_in   [131072,192]x[192,1020]
    gemm_bf16<<<dim3((HID2 + 63) / 64, NPIX / 128, 1), 256>>>(p_y, CDIM, 0, w_in, 0, nullptr,
                                                              p_upre, NPIX, CDIM, CDIM, HID2);
    // 10. depthwise 3x3 + GELU gate fused -> ug [131072,510] (lda 512, zero-padded)
    dwconv_ffn_gate<<<NPIX, 512>>>(p_upre, w_ffn_dw, p_ug);
    // 11. out = x1 + ug @ w_out   [131072,510(pad512)]x[510,192]
    gemm_bf16<<<dim3(CDIM / 64, NPIX / 128, 1), 256>>>(p_ug, UGLD, 0, w_out, 0, p_x1,
                                                       out, NPIX, UGLD, HID, CDIM);
    (void)in_sizes; (void)n_in; (void)out_size;
}